// round 14
// baseline (speedup 1.0000x reference)
#include <cuda_runtime.h>
#include <float.h>

// Scratch accumulators — zero-initialized at module load; reset inline by the
// last flusher of each segment (sum/maxk) and by the epilogue (counts), so
// each graph replay starts clean. Sized for B=4096, H=128.
__device__ float        g_sum[4096 * 128];     // segment sums
__device__ unsigned int g_maxk[4096 * 128];    // order-preserving max keys; 0 == -inf
__device__ int          g_counts[4096];        // contributions landed so far

// Order-preserving float<->uint key. Monotone: f1 < f2 <=> key(f1) < key(f2).
// key(x) >= 1 for all finite x, so a zero key acts as -infinity.
__device__ __forceinline__ unsigned int fkey(float f) {
    unsigned int b = __float_as_uint(f);
    return (b & 0x80000000u) ? ~b : (b | 0x80000000u);
}
__device__ __forceinline__ float funkey(unsigned int k) {
    return __uint_as_float((k & 0x80000000u) ? (k & 0x7FFFFFFFu) : ~k);
}

struct Acc {
    float4 s, m;
    int cnt, cur;
};

// Flush this warp's partial segment to scratch. The unique warp whose count
// contribution completes the segment (release/acquire via g_counts) also
// finalizes it: reads back the fully-accumulated scratch, writes
// [sum|mean|max] to out, and resets the scratch. g_counts is left non-zero
// as a "segment written" marker for the epilogue.
__device__ void flush_seg(const Acc& a, int lane, int B,
                          const int* __restrict__ batch, int N,
                          float* __restrict__ out) {
    int cc = min(max(a.cur, 0), B - 1);
    float* sb = g_sum + cc * 128 + lane * 4;
    atomicAdd(sb + 0, a.s.x);
    atomicAdd(sb + 1, a.s.y);
    atomicAdd(sb + 2, a.s.z);
    atomicAdd(sb + 3, a.s.w);
    unsigned int* mb = g_maxk + cc * 128 + lane * 4;
    atomicMax(mb + 0, fkey(a.m.x));
    atomicMax(mb + 1, fkey(a.m.y));
    atomicMax(mb + 2, fkey(a.m.z));
    atomicMax(mb + 3, fkey(a.m.w));

    __threadfence();      // release: this warp's sums/maxes visible in L2
    __syncwarp();         // all lanes' atomics+fences before the count add
    int old = 0;
    if (lane == 0) old = atomicAdd(&g_counts[cc], a.cnt);
    old = __shfl_sync(0xffffffffu, old, 0);

    // Total rows of segment cc via binary search on the sorted batch array
    // (all lanes search the same path -> broadcast L1 loads).
    int lo = 0, hi = N;
    while (lo < hi) {               // lower_bound(cc)
        int mid = (lo + hi) >> 1;
        if (__ldg(&batch[mid]) < cc) lo = mid + 1; else hi = mid;
    }
    int lower = lo;
    hi = N;
    while (lo < hi) {               // upper_bound(cc)
        int mid = (lo + hi) >> 1;
        if (__ldg(&batch[mid]) <= cc) lo = mid + 1; else hi = mid;
    }
    int total = lo - lower;

    if (old + a.cnt == total) {
        // Last contributor: every other flush for cc (atomics + fence) is
        // already visible. Read scratch L2-side (__ldcg) and finalize.
        __threadfence();
        int i = cc * 32 + lane;
        float4 s = __ldcg(((const float4*)g_sum) + i);
        uint4  k = __ldcg(((const uint4*)g_maxk) + i);
        float inv = 1.0f / (float)total;   // total > 0 on this path
        float4 mean = make_float4(s.x * inv, s.y * inv, s.z * inv, s.w * inv);
        float4 mx = make_float4(funkey(k.x), funkey(k.y), funkey(k.z), funkey(k.w));

        float4* row = (float4*)(out + (long long)cc * 384);
        __stcs(row + lane,      s);
        __stcs(row + 32 + lane, mean);
        __stcs(row + 64 + lane, mx);

        // Reset sum/max scratch for the next replay (counts reset in epilogue).
        ((float4*)g_sum)[i] = make_float4(0.f, 0.f, 0.f, 0.f);
        ((uint4*)g_maxk)[i] = make_uint4(0u, 0u, 0u, 0u);
    }
}

__device__ __forceinline__ void step_acc(Acc& a, int b, float4 v, int lane,
                                         int B, const int* __restrict__ batch,
                                         int N, float* __restrict__ out) {
    if (b != a.cur) {
        flush_seg(a, lane, B, batch, N, out);
        a.s = make_float4(0.f, 0.f, 0.f, 0.f);
        a.m = make_float4(-FLT_MAX, -FLT_MAX, -FLT_MAX, -FLT_MAX);
        a.cnt = 0;
        a.cur = b;
    }
    a.s.x += v.x; a.s.y += v.y; a.s.z += v.z; a.s.w += v.w;
    a.m.x = fmaxf(a.m.x, v.x);
    a.m.y = fmaxf(a.m.y, v.y);
    a.m.z = fmaxf(a.m.z, v.z);
    a.m.w = fmaxf(a.m.w, v.w);
    a.cnt++;
}

// One warp per contiguous row range (4-row aligned). Lanes each own a float4
// (4 features) of the 128-wide row; loads batched 4 rows deep for MLP.
// Register accumulation; atomic flush on segment change; the segment's last
// flusher finalizes it inline (no separate finalize pass, no grid barrier).
__global__ void __launch_bounds__(256, 8) agg_kernel(
    const float4* __restrict__ x,       // [N, 32] float4 view of [N, 128]
    const int* __restrict__ batch,      // [N] sorted segment ids (int32)
    float* __restrict__ out,            // [B, 384]
    int N, int B)
{
    int gtid   = blockIdx.x * blockDim.x + threadIdx.x;
    int warp   = gtid >> 5;
    int lane   = gtid & 31;
    int nwarps = (gridDim.x * blockDim.x) >> 5;

    // 4-row-aligned contiguous ranges (keeps int4 batch loads aligned).
    long long start = (((long long)N * warp / nwarps) + 3) & ~3LL;
    long long end   = (((long long)N * (warp + 1) / nwarps) + 3) & ~3LL;
    if (end > N) end = N;
    if (start >= end) return;

    Acc a;
    a.s = make_float4(0.f, 0.f, 0.f, 0.f);
    a.m = make_float4(-FLT_MAX, -FLT_MAX, -FLT_MAX, -FLT_MAX);
    a.cnt = 0;
    a.cur = __ldcs(&batch[start]);

    long long r = start;
    for (; r + 4 <= end; r += 4) {
        int4 b4 = __ldcs((const int4*)&batch[r]);
        float4 v0 = __ldcs(&x[(r + 0) * 32 + lane]);
        float4 v1 = __ldcs(&x[(r + 1) * 32 + lane]);
        float4 v2 = __ldcs(&x[(r + 2) * 32 + lane]);
        float4 v3 = __ldcs(&x[(r + 3) * 32 + lane]);
        step_acc(a, b4.x, v0, lane, B, batch, N, out);
        step_acc(a, b4.y, v1, lane, B, batch, N, out);
        step_acc(a, b4.z, v2, lane, B, batch, N, out);
        step_acc(a, b4.w, v3, lane, B, batch, N, out);
    }
    for (; r < end; ++r) {
        int b = __ldcs(&batch[r]);
        float4 v = __ldcs(&x[r * 32 + lane]);
        step_acc(a, b, v, lane, B, batch, N, out);
    }

    flush_seg(a, lane, B, batch, N, out);
}

// Epilogue: reset counts for the next replay; zero-fill rows of any empty
// segment (no flusher ever wrote them). One thread per segment.
__global__ void epilogue_kernel(float* __restrict__ out, int B) {
    int b = blockIdx.x * blockDim.x + threadIdx.x;
    if (b >= B) return;
    int c = g_counts[b];
    g_counts[b] = 0;
    if (c == 0) {
        float4 z = make_float4(0.f, 0.f, 0.f, 0.f);
        float4* row = (float4*)(out + (long long)b * 384);
        #pragma unroll 8
        for (int j = 0; j < 96; ++j) __stcs(row + j, z);
    }
}

extern "C" void kernel_launch(void* const* d_in, const int* in_sizes, int n_in,
                              void* d_out, int out_size) {
    const float4* x  = (const float4*)d_in[0];
    const int* batch = (const int*)d_in[1];   // int32 on device (verified)
    float* out       = (float*)d_out;

    int N = in_sizes[1];           // number of rows
    int B = out_size / 384;        // segments (out is [B, 3*128])

    // Main aggregation + inline finalize: 1216 blocks x 256 threads.
    agg_kernel<<<1216, 256>>>(x, batch, out, N, B);

    // Tiny epilogue: reset counts + handle empty segments.
    epilogue_kernel<<<(B + 255) / 256, 256>>>(out, B);
}

// round 15
// speedup vs baseline: 1.5311x; 1.5311x over previous
#include <cuda_runtime.h>
#include <float.h>

// Scratch accumulators — zero-initialized at module load; reset inline by the
// last flusher of each segment so each graph replay starts clean. B=4096, H=128.
__device__ float        g_sum[4096 * 128];     // segment sums
__device__ unsigned int g_maxk[4096 * 128];    // order-preserving max keys; 0 == -inf
__device__ int          g_counts[4096];        // contributions landed so far

// Order-preserving float<->uint key. Monotone: f1 < f2 <=> key(f1) < key(f2).
// key(x) >= 1 for all finite x, so a zero key acts as -infinity.
__device__ __forceinline__ unsigned int fkey(float f) {
    unsigned int b = __float_as_uint(f);
    return (b & 0x80000000u) ? ~b : (b | 0x80000000u);
}
__device__ __forceinline__ float funkey(unsigned int k) {
    return __uint_as_float((k & 0x80000000u) ? (k & 0x7FFFFFFFu) : ~k);
}

// COLD PATH — deliberately __noinline__ so the hot loop stays lean (R14
// regression root cause was this code inlined 4x into the loop).
// Flush this warp's partial segment to scratch; the unique warp whose count
// contribution completes the segment (release/acquire via g_counts) also:
//   - finalizes it (reads scratch, writes [sum|mean|max] to out),
//   - resets the segment's scratch and count for the next replay,
//   - zero-fills the out rows of any empty segments between this segment and
//     the next existing one (and before the first existing segment).
__device__ __noinline__ void flush_seg(float4 s, float4 m, int cnt, int cur,
                                       int lane, int B,
                                       const int* __restrict__ batch, int N,
                                       float* __restrict__ out) {
    int cc = min(max(cur, 0), B - 1);
    float* sb = g_sum + cc * 128 + lane * 4;
    atomicAdd(sb + 0, s.x);
    atomicAdd(sb + 1, s.y);
    atomicAdd(sb + 2, s.z);
    atomicAdd(sb + 3, s.w);
    unsigned int* mb = g_maxk + cc * 128 + lane * 4;
    atomicMax(mb + 0, fkey(m.x));
    atomicMax(mb + 1, fkey(m.y));
    atomicMax(mb + 2, fkey(m.z));
    atomicMax(mb + 3, fkey(m.w));

    __threadfence();      // release: this warp's sums/maxes visible in L2
    __syncwarp();         // all lanes' atomics+fences before the count add
    int old = 0;
    if (lane == 0) old = atomicAdd(&g_counts[cc], cnt);
    old = __shfl_sync(0xffffffffu, old, 0);

    // Segment extent via binary search on the sorted batch array (all lanes
    // follow the same path -> broadcast loads, L1/L2-hot).
    int lo = 0, hi = N;
    while (lo < hi) {               // lower_bound(cc)
        int mid = (lo + hi) >> 1;
        if (__ldg(&batch[mid]) < cc) lo = mid + 1; else hi = mid;
    }
    int lower = lo;
    hi = N;
    while (lo < hi) {               // upper_bound(cc)
        int mid = (lo + hi) >> 1;
        if (__ldg(&batch[mid]) <= cc) lo = mid + 1; else hi = mid;
    }
    int upper = lo;
    int total = upper - lower;

    if (old + cnt == total) {
        // Last contributor: all flushes for cc are visible. Finalize.
        __threadfence();
        int i = cc * 32 + lane;
        float4 sv = __ldcg(((const float4*)g_sum) + i);
        uint4  kv = __ldcg(((const uint4*)g_maxk) + i);
        float inv = 1.0f / (float)total;     // total > 0 on this path
        float4 mean = make_float4(sv.x * inv, sv.y * inv, sv.z * inv, sv.w * inv);
        float4 mx = make_float4(funkey(kv.x), funkey(kv.y),
                                funkey(kv.z), funkey(kv.w));

        float4* row = (float4*)(out + (long long)cc * 384);
        __stcs(row + lane,      sv);
        __stcs(row + 32 + lane, mean);
        __stcs(row + 64 + lane, mx);

        // Reset scratch + count for the next replay.
        ((float4*)g_sum)[i] = make_float4(0.f, 0.f, 0.f, 0.f);
        ((uint4*)g_maxk)[i] = make_uint4(0u, 0u, 0u, 0u);
        if (lane == 0) g_counts[cc] = 0;

        // Zero-fill empty segments: (cc, next existing) and, if this is the
        // globally first segment, [0, cc).
        int nxt = (upper < N) ? min(max(__ldg(&batch[upper]), 0), B - 1) : B;
        float4 z = make_float4(0.f, 0.f, 0.f, 0.f);
        for (int e = cc + 1; e < nxt; ++e) {
            float4* er = (float4*)(out + (long long)e * 384);
            __stcs(er + lane,      z);
            __stcs(er + 32 + lane, z);
            __stcs(er + 64 + lane, z);
        }
        if (lower == 0) {
            for (int e = 0; e < cc; ++e) {
                float4* er = (float4*)(out + (long long)e * 384);
                __stcs(er + lane,      z);
                __stcs(er + 32 + lane, z);
                __stcs(er + 64 + lane, z);
            }
        }
    }
}

struct Acc {
    float4 s, m;
    int cnt, cur;
};

__device__ __forceinline__ void step_acc(Acc& a, int b, float4 v, int lane,
                                         int B, const int* __restrict__ batch,
                                         int N, float* __restrict__ out) {
    if (b != a.cur) {
        flush_seg(a.s, a.m, a.cnt, a.cur, lane, B, batch, N, out);
        a.s = make_float4(0.f, 0.f, 0.f, 0.f);
        a.m = make_float4(-FLT_MAX, -FLT_MAX, -FLT_MAX, -FLT_MAX);
        a.cnt = 0;
        a.cur = b;
    }
    a.s.x += v.x; a.s.y += v.y; a.s.z += v.z; a.s.w += v.w;
    a.m.x = fmaxf(a.m.x, v.x);
    a.m.y = fmaxf(a.m.y, v.y);
    a.m.z = fmaxf(a.m.z, v.z);
    a.m.w = fmaxf(a.m.w, v.w);
    a.cnt++;
}

// One warp per contiguous row range (4-row aligned). Lanes each own a float4
// (4 features) of the 128-wide row; loads batched 4 rows deep for MLP.
// Register accumulation; out-of-line flush on segment change; the segment's
// last flusher finalizes it inline. Single kernel, no barrier, no epilogue.
__global__ void __launch_bounds__(256) agg_kernel(
    const float4* __restrict__ x,       // [N, 32] float4 view of [N, 128]
    const int* __restrict__ batch,      // [N] sorted segment ids (int32)
    float* __restrict__ out,            // [B, 384]
    int N, int B)
{
    int gtid   = blockIdx.x * blockDim.x + threadIdx.x;
    int warp   = gtid >> 5;
    int lane   = gtid & 31;
    int nwarps = (gridDim.x * blockDim.x) >> 5;

    // 4-row-aligned contiguous ranges (keeps int4 batch loads aligned).
    long long start = (((long long)N * warp / nwarps) + 3) & ~3LL;
    long long end   = (((long long)N * (warp + 1) / nwarps) + 3) & ~3LL;
    if (end > N) end = N;
    if (start >= end) return;

    Acc a;
    a.s = make_float4(0.f, 0.f, 0.f, 0.f);
    a.m = make_float4(-FLT_MAX, -FLT_MAX, -FLT_MAX, -FLT_MAX);
    a.cnt = 0;
    a.cur = __ldcs(&batch[start]);

    long long r = start;
    for (; r + 4 <= end; r += 4) {
        int4 b4 = __ldcs((const int4*)&batch[r]);
        float4 v0 = __ldcs(&x[(r + 0) * 32 + lane]);
        float4 v1 = __ldcs(&x[(r + 1) * 32 + lane]);
        float4 v2 = __ldcs(&x[(r + 2) * 32 + lane]);
        float4 v3 = __ldcs(&x[(r + 3) * 32 + lane]);
        step_acc(a, b4.x, v0, lane, B, batch, N, out);
        step_acc(a, b4.y, v1, lane, B, batch, N, out);
        step_acc(a, b4.z, v2, lane, B, batch, N, out);
        step_acc(a, b4.w, v3, lane, B, batch, N, out);
    }
    for (; r < end; ++r) {
        int b = __ldcs(&batch[r]);
        float4 v = __ldcs(&x[r * 32 + lane]);
        step_acc(a, b, v, lane, B, batch, N, out);
    }

    flush_seg(a.s, a.m, a.cnt, a.cur, lane, B, batch, N, out);
}

extern "C" void kernel_launch(void* const* d_in, const int* in_sizes, int n_in,
                              void* d_out, int out_size) {
    const float4* x  = (const float4*)d_in[0];
    const int* batch = (const int*)d_in[1];   // int32 on device (verified)
    float* out       = (float*)d_out;

    int N = in_sizes[1];           // number of rows
    int B = out_size / 384;        // segments (out is [B, 3*128])

    // Single launch: aggregation + inline last-arriver finalize.
    agg_kernel<<<1216, 256>>>(x, batch, out, N, B);
}

// round 16
// speedup vs baseline: 1.7479x; 1.1416x over previous
#include <cuda_runtime.h>
#include <float.h>

// Scratch accumulators — zero-initialized at module load, re-zeroed by
// finalize_kernel every invocation so each graph replay starts clean.
__device__ float        g_sum[4096 * 128];     // segment sums
__device__ unsigned int g_maxk[4096 * 128];    // order-preserving max keys; 0 == -inf
__device__ int          g_counts[4096];        // segment element counts

// Order-preserving float<->uint key. Monotone: f1 < f2 <=> key(f1) < key(f2).
// key(x) >= 1 for all finite x, so a zero key acts as -infinity.
__device__ __forceinline__ unsigned int fkey(float f) {
    unsigned int b = __float_as_uint(f);
    return (b & 0x80000000u) ? ~b : (b | 0x80000000u);
}
__device__ __forceinline__ float funkey(unsigned int k) {
    return __uint_as_float((k & 0x80000000u) ? (k & 0x7FFFFFFFu) : ~k);
}

struct Acc {
    float4 s, m;
    int cnt, cur;
};

__device__ __forceinline__ void flush_acc(const Acc& a, int lane, int B) {
    int cc = min(max(a.cur, 0), B - 1);
    float* sb = g_sum + cc * 128 + lane * 4;
    atomicAdd(sb + 0, a.s.x);
    atomicAdd(sb + 1, a.s.y);
    atomicAdd(sb + 2, a.s.z);
    atomicAdd(sb + 3, a.s.w);
    unsigned int* mb = g_maxk + cc * 128 + lane * 4;
    atomicMax(mb + 0, fkey(a.m.x));
    atomicMax(mb + 1, fkey(a.m.y));
    atomicMax(mb + 2, fkey(a.m.z));
    atomicMax(mb + 3, fkey(a.m.w));
    if (lane == 0) atomicAdd(&g_counts[cc], a.cnt);
}

__device__ __forceinline__ void step_acc(Acc& a, int b, float4 v,
                                         int lane, int B) {
    if (b != a.cur) {
        flush_acc(a, lane, B);
        a.s = make_float4(0.f, 0.f, 0.f, 0.f);
        a.m = make_float4(-FLT_MAX, -FLT_MAX, -FLT_MAX, -FLT_MAX);
        a.cnt = 0;
        a.cur = b;
    }
    a.s.x += v.x; a.s.y += v.y; a.s.z += v.z; a.s.w += v.w;
    a.m.x = fmaxf(a.m.x, v.x);
    a.m.y = fmaxf(a.m.y, v.y);
    a.m.z = fmaxf(a.m.z, v.z);
    a.m.w = fmaxf(a.m.w, v.w);
    a.cnt++;
}

// One warp per contiguous row range (4-row aligned). Lanes each own a float4
// (4 features) of the 128-wide row. Rows processed in chunks of 4 with all
// loads issued up-front to hide the ~577-cyc DRAM latency. Accumulate
// sum/max/count in registers; flush to scratch atomically on segment change.
// (Byte-identical to the R8 hot kernel: 30 regs, ~7 TB/s. Do not add state.)
__global__ void __launch_bounds__(256) agg_kernel(
    const float4* __restrict__ x,       // [N, 32] float4 view of [N, 128]
    const int* __restrict__ batch,      // [N] sorted segment ids (int32)
    int N, int B)
{
    int gtid   = blockIdx.x * blockDim.x + threadIdx.x;
    int warp   = gtid >> 5;
    int lane   = gtid & 31;
    int nwarps = (gridDim.x * blockDim.x) >> 5;

    // 4-row-aligned contiguous ranges (keeps int4 batch loads aligned).
    long long start = (((long long)N * warp / nwarps) + 3) & ~3LL;
    long long end   = (((long long)N * (warp + 1) / nwarps) + 3) & ~3LL;
    if (end > N) end = N;
    if (start >= end) return;

    Acc a;
    a.s = make_float4(0.f, 0.f, 0.f, 0.f);
    a.m = make_float4(-FLT_MAX, -FLT_MAX, -FLT_MAX, -FLT_MAX);
    a.cnt = 0;
    a.cur = __ldcs(&batch[start]);

    long long r = start;
    for (; r + 4 <= end; r += 4) {
        int4 b4 = __ldcs((const int4*)&batch[r]);
        float4 v0 = __ldcs(&x[(r + 0) * 32 + lane]);
        float4 v1 = __ldcs(&x[(r + 1) * 32 + lane]);
        float4 v2 = __ldcs(&x[(r + 2) * 32 + lane]);
        float4 v3 = __ldcs(&x[(r + 3) * 32 + lane]);
        step_acc(a, b4.x, v0, lane, B);
        step_acc(a, b4.y, v1, lane, B);
        step_acc(a, b4.z, v2, lane, B);
        step_acc(a, b4.w, v3, lane, B);
    }
    for (; r < end; ++r) {
        int b = __ldcs(&batch[r]);
        float4 v = __ldcs(&x[r * 32 + lane]);
        step_acc(a, b, v, lane, B);
    }

    flush_acc(a, lane, B);
}

__device__ __forceinline__ void finalize_item(int i, float* __restrict__ out) {
    int b  = i >> 5;        // segment
    int h4 = i & 31;        // float4 group within 128 features

    float4 s = ((const float4*)g_sum)[i];
    uint4  k = ((const uint4*)g_maxk)[i];
    int    c = g_counts[b];
    __syncwarp();           // segment's 32 items live in one warp: order
                            // all count reads before the lane-0 reset

    float inv = 1.0f / fmaxf((float)c, 1.0f);
    float4 mean = make_float4(s.x * inv, s.y * inv, s.z * inv, s.w * inv);
    float4 mx;
    if (c > 0) {
        mx = make_float4(funkey(k.x), funkey(k.y), funkey(k.z), funkey(k.w));
    } else {
        mx = make_float4(0.f, 0.f, 0.f, 0.f);
    }

    float4* row = (float4*)(out + (long long)b * 384);
    __stcs(row + h4,      s);
    __stcs(row + 32 + h4, mean);
    __stcs(row + 64 + h4, mx);

    // Reset scratch for next replay.
    ((float4*)g_sum)[i] = make_float4(0.f, 0.f, 0.f, 0.f);
    ((uint4*)g_maxk)[i] = make_uint4(0u, 0u, 0u, 0u);
    if (h4 == 0) g_counts[b] = 0;
}

// PDL finalize: blocks pre-launch while agg drains, park on the grid
// dependency, then each thread handles 2 independent items (2 load chains).
__global__ void __launch_bounds__(256) finalize_kernel(float* __restrict__ out, int B) {
    cudaGridDependencySynchronize();   // wait until agg_kernel fully complete

    int tid   = blockIdx.x * blockDim.x + threadIdx.x;
    int half  = B * 16;                // B*32 items total, 2 per thread
    if (tid < half) {
        finalize_item(tid, out);
        finalize_item(tid + half, out);
    }
}

extern "C" void kernel_launch(void* const* d_in, const int* in_sizes, int n_in,
                              void* d_out, int out_size) {
    const float4* x  = (const float4*)d_in[0];
    const int* batch = (const int*)d_in[1];   // int32 on device (verified)
    float* out       = (float*)d_out;

    int N = in_sizes[1];           // number of rows
    int B = out_size / 384;        // segments (out is [B, 3*128])

    // Main aggregation: 1216 blocks x 256 threads (R8 config, ~7 TB/s).
    agg_kernel<<<1216, 256>>>(x, batch, N, B);

    // Finalize with programmatic dependent launch: overlap its launch/ramp
    // with the agg tail; cudaGridDependencySynchronize gates correctness.
    {
        int threads = 256;
        int blocks  = (B * 16 + threads - 1) / threads;   // 2 items/thread
        cudaLaunchConfig_t cfg = {};
        cfg.gridDim  = dim3(blocks, 1, 1);
        cfg.blockDim = dim3(threads, 1, 1);
        cudaLaunchAttribute attr[1];
        attr[0].id = cudaLaunchAttributeProgrammaticStreamSerialization;
        attr[0].val.programmaticStreamSerializationAllowed = 1;
        cfg.attrs    = attr;
        cfg.numAttrs = 1;
        cudaLaunchKernelEx(&cfg, finalize_kernel, out, B);
    }
}